// round 15
// baseline (speedup 1.0000x reference)
#include <cuda_runtime.h>
#include <cuda_bf16.h>
#include <cstdint>

// ---------------- problem constants ----------------
#define B_       2048
#define F_       7
#define CARD_    10000
#define E_       64
#define CONCAT_  256
#define NH_      512        // P_HID
#define NBLK_    2176       // # of k16 blocks in 16-aligned upper triangle
#define KSPLIT_  4          // gemm split-K (256 CTAs = one clean wave @2/SM)
#define CHUNKS_PER_SPLIT_ 136   // 4 splits x 136 chunks x 4 blocks = 2176
#define NFOLD_   8          // fold launch slices (independent of gemm splits)
#define BLOCKS_PER_FOLD_ 272
#define MT_      128
#define NT_      128
#define FROWS_   4
#define FBLK_    (B_ / FROWS_)   // 512 feature blocks

// c_s: [128][264] bf16, w stage: [64][136] bf16
#define CS_STRIDE 264
#define WS_STRIDE 136
#define CS_BYTES  (128 * CS_STRIDE * 2)
#define WS_BYTES  (64 * WS_STRIDE * 2)
#define SMEM_BYTES (CS_BYTES + 2 * WS_BYTES)   // 102400

// ---------------- device scratch ----------------
__device__ alignas(256) __nv_bfloat16 g_Ws[(size_t)NBLK_ * 16 * NH_];  // 35.7 MB folded weights
__device__ alignas(256) __nv_bfloat16 g_Cb[(size_t)B_ * CONCAT_];      // 1 MB concat features
__device__ alignas(256) float         g_P[(size_t)KSPLIT_ * B_ * NH_]; // 16 MB split-K partials
__device__ alignas(16)  uchar2        g_blk[NBLK_];

__device__ __forceinline__ uchar2 blk_decode(int t) {
    int acc = 0, g = 0, cum = 0;
#pragma unroll
    for (int h = 0; h < 16; h++) {
        acc += 16 * (16 - h);
        if (t >= acc) { g = h + 1; cum = acc; }
    }
    int r = t - cum;
    int per = 16 - g;
    int i = 16 * g + r / per;
    int j0 = 16 * (g + r % per);
    uchar2 o; o.x = (unsigned char)i; o.y = (unsigned char)j0;
    return o;
}

__device__ __forceinline__ void cp_async16(unsigned daddr, const void* src) {
    asm volatile("cp.async.cg.shared.global [%0], [%1], 16;\n" :: "r"(daddr), "l"(src));
}

// ---------------- kernel: feature MLPs ----------------
__global__ void __launch_bounds__(256) k_feat(
    const float* __restrict__ dense, const int* __restrict__ sparse,
    const float* __restrict__ emb,
    const float* __restrict__ dw1, const float* __restrict__ db1,
    const float* __restrict__ dw2, const float* __restrict__ db2,
    const float* __restrict__ sw1, const float* __restrict__ sb1,
    const float* __restrict__ sw2, const float* __restrict__ sb2) {
    __shared__ float sd[FROWS_][16];
    __shared__ float sh[FROWS_][64];
    __shared__ float se[FROWS_][64];
    const int tid = threadIdx.x;
    const int grp = tid >> 6, t = tid & 63;
    const int b = blockIdx.x * FROWS_ + grp;

    if (t < 13) sd[grp][t] = dense[b * 13 + t];
    __syncthreads();
    float h = db1[t];
#pragma unroll
    for (int d = 0; d < 13; d++) h += sd[grp][d] * dw1[d * 64 + t];
    sh[grp][t] = fmaxf(h, 0.f);
    __syncthreads();
    if (t < 32) {
        float o = db2[t];
#pragma unroll
        for (int k = 0; k < 64; k++) o += sh[grp][k] * dw2[k * 32 + t];
        g_Cb[(size_t)b * CONCAT_ + t] = __float2bfloat16(o);
    }
    for (int f = 0; f < F_; f++) {
        __syncthreads();
        int idx = sparse[b * F_ + f];
        idx = min(max(idx, 0), CARD_ - 1);
        se[grp][t] = emb[((size_t)f * CARD_ + idx) * E_ + t];
        __syncthreads();
        float hh = sb1[f * 64 + t];
#pragma unroll
        for (int e = 0; e < 64; e++) hh += se[grp][e] * sw1[((size_t)f * 64 + e) * 64 + t];
        sh[grp][t] = fmaxf(hh, 0.f);
        __syncthreads();
        if (t < 32) {
            float o = sb2[f * 32 + t];
#pragma unroll
            for (int k = 0; k < 64; k++) o += sh[grp][k] * sw2[((size_t)f * 64 + k) * 32 + t];
            g_Cb[(size_t)b * CONCAT_ + 32 + f * 32 + t] = __float2bfloat16(o);
        }
    }
}

// ---------------- kernel: weight fold for one slice z ----------------
__global__ void __launch_bounds__(256) k_fold(const float* __restrict__ pw1, int z) {
    const int fb = z * BLOCKS_PER_FOLD_ + blockIdx.x;
    const int tid = threadIdx.x;
    const uchar2 bl = blk_decode(fb);
    if (tid == 0) g_blk[fb] = bl;
    const int i = bl.x, j0 = bl.y;
    const int w = tid >> 5;                  // warp -> kk rows w, w+8
    const int l = tid & 31;
    int kkv[2] = {w, w + 8};

    float4 va[2][4], ub[2][4];
    bool ge[2], gt[2];
#pragma unroll
    for (int rr = 0; rr < 2; rr++) {
        int j = j0 + kkv[rr];
        ge[rr] = (j >= i); gt[rr] = (j > i);
        const float4* pA = reinterpret_cast<const float4*>(pw1 + ((size_t)(i << 8) + j) * NH_);
#pragma unroll
        for (int c = 0; c < 4; c++)
            va[rr][c] = ge[rr] ? pA[l + 32 * c] : make_float4(0.f, 0.f, 0.f, 0.f);
    }
#pragma unroll
    for (int rr = 0; rr < 2; rr++) {
        int j = j0 + kkv[rr];
        const float4* pB = reinterpret_cast<const float4*>(pw1 + ((size_t)(j << 8) + i) * NH_);
#pragma unroll
        for (int c = 0; c < 4; c++)
            ub[rr][c] = gt[rr] ? pB[l + 32 * c] : make_float4(0.f, 0.f, 0.f, 0.f);
    }
#pragma unroll
    for (int rr = 0; rr < 2; rr++) {
        __nv_bfloat16* dst = g_Ws + ((size_t)fb * 16 + kkv[rr]) * NH_;
#pragma unroll
        for (int c = 0; c < 4; c++) {
            float4 v = va[rr][c], u = ub[rr][c];
            v.x += u.x; v.y += u.y; v.z += u.z; v.w += u.w;
            __nv_bfloat162 lo = __floats2bfloat162_rn(v.x, v.y);
            __nv_bfloat162 hi = __floats2bfloat162_rn(v.z, v.w);
            uint2 o;
            o.x = *reinterpret_cast<unsigned*>(&lo);
            o.y = *reinterpret_cast<unsigned*>(&hi);
            *reinterpret_cast<uint2*>(dst + 4 * (l + 32 * c)) = o;
        }
    }
}

// ---------------- kernel: triangular interaction GEMM (split-K via blockIdx.z) ----------------
__device__ __forceinline__ void mma16816(float* d, const unsigned* a, unsigned b0, unsigned b1) {
    asm volatile(
        "mma.sync.aligned.m16n8k16.row.col.f32.bf16.bf16.f32 "
        "{%0,%1,%2,%3}, {%4,%5,%6,%7}, {%8,%9}, {%0,%1,%2,%3};\n"
        : "+f"(d[0]), "+f"(d[1]), "+f"(d[2]), "+f"(d[3])
        : "r"(a[0]), "r"(a[1]), "r"(a[2]), "r"(a[3]), "r"(b0), "r"(b1));
}

__device__ __forceinline__ void w_prefetch(unsigned wst_u32, int t0, int nbase, int tid) {
    const uint4* wsrc = reinterpret_cast<const uint4*>(g_Ws + (size_t)t0 * 16 * NH_ + nbase);
#pragma unroll
    for (int it = 0; it < 4; it++) {
        int idx = tid + it * 256;
        int kr = idx >> 4, nc = idx & 15;
        cp_async16(wst_u32 + kr * (WS_STRIDE * 2) + nc * 16, wsrc + kr * 64 + nc);
    }
}

__global__ void __launch_bounds__(256, 2) k_gemm() {
    extern __shared__ char smem[];
    __nv_bfloat16* c_s = reinterpret_cast<__nv_bfloat16*>(smem);
    const unsigned w_base_u32 = (unsigned)__cvta_generic_to_shared(smem + CS_BYTES);

    const int tid  = threadIdx.x;
    const int lane = tid & 31;
    const int warp = tid >> 5;
    const int wm   = warp & 3;
    const int wn   = warp >> 2;
    const int g    = lane >> 2;
    const int tg   = lane & 3;

    const int mbase = blockIdx.x * MT_;
    const int nbase = blockIdx.y * NT_;
    const int ks    = blockIdx.z;
    const int tch0  = ks * CHUNKS_PER_SPLIT_;

    {
        const uint4* src = reinterpret_cast<const uint4*>(g_Cb + (size_t)mbase * CONCAT_);
        for (int i = tid; i < 128 * 32; i += 256) {
            int r = i >> 5, c = i & 31;
            *reinterpret_cast<uint4*>(c_s + r * CS_STRIDE + c * 8) = src[r * 32 + c];
        }
    }

    float acc[2][8][4];
#pragma unroll
    for (int a = 0; a < 2; a++)
#pragma unroll
        for (int b2 = 0; b2 < 8; b2++)
#pragma unroll
            for (int c2 = 0; c2 < 4; c2++) acc[a][b2][c2] = 0.f;

    unsigned w_lane_off;
    {
        int mat = lane >> 3, rl = lane & 7;
        int krow = ((mat & 1) << 3) + rl;
        int ncol = wn * 64 + ((mat >> 1) << 3);
        w_lane_off = 2u * (krow * WS_STRIDE + ncol);
    }

    w_prefetch(w_base_u32, tch0 * 4, nbase, tid);
    asm volatile("cp.async.commit_group;\n");

    for (int c = 0; c < CHUNKS_PER_SPLIT_; c++) {
        const int t0 = (tch0 + c) * 4;

        asm volatile("cp.async.wait_group 0;\n");
        __syncthreads();

        if (c + 1 < CHUNKS_PER_SPLIT_) {
            w_prefetch(w_base_u32 + ((c + 1) & 1) * WS_BYTES, t0 + 4, nbase, tid);
            asm volatile("cp.async.commit_group;\n");
        }

        const unsigned wst = w_base_u32 + (c & 1) * WS_BYTES + w_lane_off;
        const uint2 blv = *reinterpret_cast<const uint2*>(&g_blk[t0]);

#pragma unroll
        for (int ks16 = 0; ks16 < 4; ks16++) {
            const unsigned half = (ks16 < 2) ? blv.x : blv.y;
            const int ii = (half >> ((ks16 & 1) * 16)) & 0xff;
            const int jb = (half >> ((ks16 & 1) * 16 + 8)) & 0xff;

            unsigned bf[4][4];
#pragma unroll
            for (int ng = 0; ng < 4; ng++) {
                unsigned addr = wst + 2u * (ks16 * 16 * WS_STRIDE + ng * 16);
                asm volatile(
                    "ldmatrix.sync.aligned.m8n8.x4.trans.shared.b16 {%0,%1,%2,%3}, [%4];\n"
                    : "=r"(bf[ng][0]), "=r"(bf[ng][1]), "=r"(bf[ng][2]), "=r"(bf[ng][3])
                    : "r"(addr));
            }

            unsigned af[2][4];
#pragma unroll
            for (int mt = 0; mt < 2; mt++) {
                int r1 = wm * 32 + mt * 16 + g;
                __nv_bfloat162 x0 = __bfloat162bfloat162(c_s[r1 * CS_STRIDE + ii]);
                __nv_bfloat162 x1 = __bfloat162bfloat162(c_s[(r1 + 8) * CS_STRIDE + ii]);
                const __nv_bfloat162* p1 =
                    reinterpret_cast<const __nv_bfloat162*>(c_s + r1 * CS_STRIDE + jb + 2 * tg);
                const __nv_bfloat162* p2 =
                    reinterpret_cast<const __nv_bfloat162*>(c_s + (r1 + 8) * CS_STRIDE + jb + 2 * tg);
                __nv_bfloat162 a0 = __hmul2(x0, p1[0]);
                __nv_bfloat162 a1 = __hmul2(x1, p2[0]);
                __nv_bfloat162 a2 = __hmul2(x0, p1[4]);
                __nv_bfloat162 a3 = __hmul2(x1, p2[4]);
                af[mt][0] = *reinterpret_cast<unsigned*>(&a0);
                af[mt][1] = *reinterpret_cast<unsigned*>(&a1);
                af[mt][2] = *reinterpret_cast<unsigned*>(&a2);
                af[mt][3] = *reinterpret_cast<unsigned*>(&a3);
            }

#pragma unroll
            for (int mt = 0; mt < 2; mt++)
#pragma unroll
                for (int ng = 0; ng < 4; ng++) {
                    mma16816(acc[mt][2 * ng],     af[mt], bf[ng][0], bf[ng][1]);
                    mma16816(acc[mt][2 * ng + 1], af[mt], bf[ng][2], bf[ng][3]);
                }
        }
    }

#pragma unroll
    for (int mt = 0; mt < 2; mt++) {
        int r1 = mbase + wm * 32 + mt * 16 + g;
#pragma unroll
        for (int nn = 0; nn < 8; nn++) {
            int col = nbase + wn * 64 + nn * 8 + 2 * tg;
            float* dst = g_P + ((size_t)ks * B_ + r1) * NH_ + col;
            *reinterpret_cast<float2*>(dst) = make_float2(acc[mt][nn][0], acc[mt][nn][1]);
            *reinterpret_cast<float2*>(dst + (size_t)8 * NH_) =
                make_float2(acc[mt][nn][2], acc[mt][nn][3]);
        }
    }
}

// ---------------- kernel: reduce splits + bias + relu + pw2 + sigmoid ----------------
__global__ void k_finalize(const float* __restrict__ pb1, const float* __restrict__ pw2,
                           const float* __restrict__ pb2, float* __restrict__ out) {
    const int b = blockIdx.x;
    const int t = threadIdx.x;
    float local = 0.f;
    for (int n = t; n < NH_; n += 128) {
        size_t o = (size_t)b * NH_ + n;
        float v = 0.f;
#pragma unroll
        for (int s = 0; s < KSPLIT_; s++) v += g_P[(size_t)s * B_ * NH_ + o];
        v = fmaxf(v + pb1[n], 0.f);
        local += v * pw2[n];
    }
#pragma unroll
    for (int off = 16; off; off >>= 1) local += __shfl_down_sync(0xffffffffu, local, off);
    __shared__ float red[4];
    if ((t & 31) == 0) red[t >> 5] = local;
    __syncthreads();
    if (t == 0) {
        float s = red[0] + red[1] + red[2] + red[3] + pb2[0];
        out[b] = 1.f / (1.f + expf(-s));
    }
}

// ---------------- streams / events (created once at load, never freed) ----------------
static cudaStream_t g_sf;
static cudaEvent_t  g_Eroot, g_Ef;
static struct PipeInit {
    PipeInit() {
        cudaStreamCreateWithFlags(&g_sf, cudaStreamNonBlocking);
        cudaEventCreateWithFlags(&g_Eroot, cudaEventDisableTiming);
        cudaEventCreateWithFlags(&g_Ef, cudaEventDisableTiming);
    }
} g_pipe_init;

// ---------------- launch ----------------
extern "C" void kernel_launch(void* const* d_in, const int* in_sizes, int n_in,
                              void* d_out, int out_size) {
    const float* dense  = (const float*)d_in[0];
    const int*   sparse = (const int*)d_in[1];   // int32 on device
    const float* emb = (const float*)d_in[3];
    const float* dw1 = (const float*)d_in[4];
    const float* db1 = (const float*)d_in[5];
    const float* dw2 = (const float*)d_in[6];
    const float* db2 = (const float*)d_in[7];
    const float* sw1 = (const float*)d_in[8];
    const float* sb1 = (const float*)d_in[9];
    const float* sw2 = (const float*)d_in[10];
    const float* sb2 = (const float*)d_in[11];
    const float* pw1 = (const float*)d_in[12];
    const float* pb1 = (const float*)d_in[13];
    const float* pw2 = (const float*)d_in[14];
    const float* pb2 = (const float*)d_in[15];
    float* out = (float*)d_out;

    cudaFuncSetAttribute(k_gemm, cudaFuncAttributeMaxDynamicSharedMemorySize, SMEM_BYTES);

    // fork: features overlap the folds (small L2 footprint; no gemm running yet)
    cudaEventRecord(g_Eroot, 0);
    cudaStreamWaitEvent(g_sf, g_Eroot, 0);
    k_feat<<<FBLK_, 256, 0, g_sf>>>(dense, sparse, emb,
                                    dw1, db1, dw2, db2, sw1, sb1, sw2, sb2);
    cudaEventRecord(g_Ef, g_sf);

    // folds: 8 sequential slice launches (measured faster than one monolithic launch)
    for (int z = 0; z < NFOLD_; z++)
        k_fold<<<BLOCKS_PER_FOLD_, 256, 0, 0>>>(pw1, z);

    // join, then ONE gemm launch, single-wave grid (16,4,4), full L2 locality
    cudaStreamWaitEvent(0, g_Ef, 0);
    k_gemm<<<dim3(B_ / MT_, NH_ / NT_, KSPLIT_), 256, SMEM_BYTES>>>();
    k_finalize<<<B_, 128>>>(pb1, pw2, pb2, out);
}

// round 16
// speedup vs baseline: 1.0092x; 1.0092x over previous
#include <cuda_runtime.h>
#include <cuda_bf16.h>
#include <cstdint>

// ---------------- problem constants ----------------
#define B_       2048
#define F_       7
#define CARD_    10000
#define E_       64
#define CONCAT_  256
#define NH_      512        // P_HID
#define NBLK_    2176       // # of k16 blocks in 16-aligned upper triangle
#define KSPLIT_  4          // gemm split-K
#define CHUNKS_PER_SPLIT_ 136   // 4 splits x 136 chunks x 4 blocks = 2176
#define NFOLD_   8          // fold slices (4 per stream x 2 streams)
#define BLOCKS_PER_FOLD_ 272
#define MT_      128
#define NT_      128
#define FROWS_   4
#define FBLK_    (B_ / FROWS_)   // 512 feature blocks

// c_s: [128][264] bf16, w stage: [64][136] bf16
#define CS_STRIDE 264
#define WS_STRIDE 136
#define CS_BYTES  (128 * CS_STRIDE * 2)
#define WS_BYTES  (64 * WS_STRIDE * 2)
#define SMEM_BYTES (CS_BYTES + 2 * WS_BYTES)   // 102400

// ---------------- device scratch ----------------
__device__ alignas(256) __nv_bfloat16 g_Ws[(size_t)NBLK_ * 16 * NH_];  // 35.7 MB folded weights
__device__ alignas(256) __nv_bfloat16 g_Cb[(size_t)B_ * CONCAT_];      // 1 MB concat features
__device__ alignas(256) float         g_P[(size_t)KSPLIT_ * B_ * NH_]; // 16 MB split-K partials
__device__ alignas(16)  uchar2        g_blk[NBLK_];

__device__ __forceinline__ uchar2 blk_decode(int t) {
    int acc = 0, g = 0, cum = 0;
#pragma unroll
    for (int h = 0; h < 16; h++) {
        acc += 16 * (16 - h);
        if (t >= acc) { g = h + 1; cum = acc; }
    }
    int r = t - cum;
    int per = 16 - g;
    int i = 16 * g + r / per;
    int j0 = 16 * (g + r % per);
    uchar2 o; o.x = (unsigned char)i; o.y = (unsigned char)j0;
    return o;
}

__device__ __forceinline__ void cp_async16(unsigned daddr, const void* src) {
    asm volatile("cp.async.cg.shared.global [%0], [%1], 16;\n" :: "r"(daddr), "l"(src));
}

// ---------------- kernel: feature MLPs ----------------
__global__ void __launch_bounds__(256) k_feat(
    const float* __restrict__ dense, const int* __restrict__ sparse,
    const float* __restrict__ emb,
    const float* __restrict__ dw1, const float* __restrict__ db1,
    const float* __restrict__ dw2, const float* __restrict__ db2,
    const float* __restrict__ sw1, const float* __restrict__ sb1,
    const float* __restrict__ sw2, const float* __restrict__ sb2) {
    __shared__ float sd[FROWS_][16];
    __shared__ float sh[FROWS_][64];
    __shared__ float se[FROWS_][64];
    const int tid = threadIdx.x;
    const int grp = tid >> 6, t = tid & 63;
    const int b = blockIdx.x * FROWS_ + grp;

    if (t < 13) sd[grp][t] = dense[b * 13 + t];
    __syncthreads();
    float h = db1[t];
#pragma unroll
    for (int d = 0; d < 13; d++) h += sd[grp][d] * dw1[d * 64 + t];
    sh[grp][t] = fmaxf(h, 0.f);
    __syncthreads();
    if (t < 32) {
        float o = db2[t];
#pragma unroll
        for (int k = 0; k < 64; k++) o += sh[grp][k] * dw2[k * 32 + t];
        g_Cb[(size_t)b * CONCAT_ + t] = __float2bfloat16(o);
    }
    for (int f = 0; f < F_; f++) {
        __syncthreads();
        int idx = sparse[b * F_ + f];
        idx = min(max(idx, 0), CARD_ - 1);
        se[grp][t] = emb[((size_t)f * CARD_ + idx) * E_ + t];
        __syncthreads();
        float hh = sb1[f * 64 + t];
#pragma unroll
        for (int e = 0; e < 64; e++) hh += se[grp][e] * sw1[((size_t)f * 64 + e) * 64 + t];
        sh[grp][t] = fmaxf(hh, 0.f);
        __syncthreads();
        if (t < 32) {
            float o = sb2[f * 32 + t];
#pragma unroll
            for (int k = 0; k < 64; k++) o += sh[grp][k] * sw2[((size_t)f * 64 + k) * 32 + t];
            g_Cb[(size_t)b * CONCAT_ + 32 + f * 32 + t] = __float2bfloat16(o);
        }
    }
}

// ---------------- kernel: weight fold for one slice z ----------------
__global__ void __launch_bounds__(256) k_fold(const float* __restrict__ pw1, int z) {
    const int fb = z * BLOCKS_PER_FOLD_ + blockIdx.x;
    const int tid = threadIdx.x;
    const uchar2 bl = blk_decode(fb);
    if (tid == 0) g_blk[fb] = bl;
    const int i = bl.x, j0 = bl.y;
    const int w = tid >> 5;                  // warp -> kk rows w, w+8
    const int l = tid & 31;
    int kkv[2] = {w, w + 8};

    float4 va[2][4], ub[2][4];
    bool ge[2], gt[2];
#pragma unroll
    for (int rr = 0; rr < 2; rr++) {
        int j = j0 + kkv[rr];
        ge[rr] = (j >= i); gt[rr] = (j > i);
        const float4* pA = reinterpret_cast<const float4*>(pw1 + ((size_t)(i << 8) + j) * NH_);
#pragma unroll
        for (int c = 0; c < 4; c++)
            va[rr][c] = ge[rr] ? pA[l + 32 * c] : make_float4(0.f, 0.f, 0.f, 0.f);
    }
#pragma unroll
    for (int rr = 0; rr < 2; rr++) {
        int j = j0 + kkv[rr];
        const float4* pB = reinterpret_cast<const float4*>(pw1 + ((size_t)(j << 8) + i) * NH_);
#pragma unroll
        for (int c = 0; c < 4; c++)
            ub[rr][c] = gt[rr] ? pB[l + 32 * c] : make_float4(0.f, 0.f, 0.f, 0.f);
    }
#pragma unroll
    for (int rr = 0; rr < 2; rr++) {
        __nv_bfloat16* dst = g_Ws + ((size_t)fb * 16 + kkv[rr]) * NH_;
#pragma unroll
        for (int c = 0; c < 4; c++) {
            float4 v = va[rr][c], u = ub[rr][c];
            v.x += u.x; v.y += u.y; v.z += u.z; v.w += u.w;
            __nv_bfloat162 lo = __floats2bfloat162_rn(v.x, v.y);
            __nv_bfloat162 hi = __floats2bfloat162_rn(v.z, v.w);
            uint2 o;
            o.x = *reinterpret_cast<unsigned*>(&lo);
            o.y = *reinterpret_cast<unsigned*>(&hi);
            *reinterpret_cast<uint2*>(dst + 4 * (l + 32 * c)) = o;
        }
    }
}

// ---------------- kernel: triangular interaction GEMM (split-K via blockIdx.z) ----------------
__device__ __forceinline__ void mma16816(float* d, const unsigned* a, unsigned b0, unsigned b1) {
    asm volatile(
        "mma.sync.aligned.m16n8k16.row.col.f32.bf16.bf16.f32 "
        "{%0,%1,%2,%3}, {%4,%5,%6,%7}, {%8,%9}, {%0,%1,%2,%3};\n"
        : "+f"(d[0]), "+f"(d[1]), "+f"(d[2]), "+f"(d[3])
        : "r"(a[0]), "r"(a[1]), "r"(a[2]), "r"(a[3]), "r"(b0), "r"(b1));
}

__device__ __forceinline__ void w_prefetch(unsigned wst_u32, int t0, int nbase, int tid) {
    const uint4* wsrc = reinterpret_cast<const uint4*>(g_Ws + (size_t)t0 * 16 * NH_ + nbase);
#pragma unroll
    for (int it = 0; it < 4; it++) {
        int idx = tid + it * 256;
        int kr = idx >> 4, nc = idx & 15;
        cp_async16(wst_u32 + kr * (WS_STRIDE * 2) + nc * 16, wsrc + kr * 64 + nc);
    }
}

__global__ void __launch_bounds__(256, 2) k_gemm() {
    extern __shared__ char smem[];
    __nv_bfloat16* c_s = reinterpret_cast<__nv_bfloat16*>(smem);
    const unsigned w_base_u32 = (unsigned)__cvta_generic_to_shared(smem + CS_BYTES);

    const int tid  = threadIdx.x;
    const int lane = tid & 31;
    const int warp = tid >> 5;
    const int wm   = warp & 3;
    const int wn   = warp >> 2;
    const int g    = lane >> 2;
    const int tg   = lane & 3;

    const int mbase = blockIdx.x * MT_;
    const int nbase = blockIdx.y * NT_;
    const int ks    = blockIdx.z;
    const int tch0  = ks * CHUNKS_PER_SPLIT_;

    {
        const uint4* src = reinterpret_cast<const uint4*>(g_Cb + (size_t)mbase * CONCAT_);
        for (int i = tid; i < 128 * 32; i += 256) {
            int r = i >> 5, c = i & 31;
            *reinterpret_cast<uint4*>(c_s + r * CS_STRIDE + c * 8) = src[r * 32 + c];
        }
    }

    float acc[2][8][4];
#pragma unroll
    for (int a = 0; a < 2; a++)
#pragma unroll
        for (int b2 = 0; b2 < 8; b2++)
#pragma unroll
            for (int c2 = 0; c2 < 4; c2++) acc[a][b2][c2] = 0.f;

    unsigned w_lane_off;
    {
        int mat = lane >> 3, rl = lane & 7;
        int krow = ((mat & 1) << 3) + rl;
        int ncol = wn * 64 + ((mat >> 1) << 3);
        w_lane_off = 2u * (krow * WS_STRIDE + ncol);
    }

    w_prefetch(w_base_u32, tch0 * 4, nbase, tid);
    asm volatile("cp.async.commit_group;\n");

    for (int c = 0; c < CHUNKS_PER_SPLIT_; c++) {
        const int t0 = (tch0 + c) * 4;

        asm volatile("cp.async.wait_group 0;\n");
        __syncthreads();

        if (c + 1 < CHUNKS_PER_SPLIT_) {
            w_prefetch(w_base_u32 + ((c + 1) & 1) * WS_BYTES, t0 + 4, nbase, tid);
            asm volatile("cp.async.commit_group;\n");
        }

        const unsigned wst = w_base_u32 + (c & 1) * WS_BYTES + w_lane_off;
        const uint2 blv = *reinterpret_cast<const uint2*>(&g_blk[t0]);

#pragma unroll
        for (int ks16 = 0; ks16 < 4; ks16++) {
            const unsigned half = (ks16 < 2) ? blv.x : blv.y;
            const int ii = (half >> ((ks16 & 1) * 16)) & 0xff;
            const int jb = (half >> ((ks16 & 1) * 16 + 8)) & 0xff;

            unsigned bf[4][4];
#pragma unroll
            for (int ng = 0; ng < 4; ng++) {
                unsigned addr = wst + 2u * (ks16 * 16 * WS_STRIDE + ng * 16);
                asm volatile(
                    "ldmatrix.sync.aligned.m8n8.x4.trans.shared.b16 {%0,%1,%2,%3}, [%4];\n"
                    : "=r"(bf[ng][0]), "=r"(bf[ng][1]), "=r"(bf[ng][2]), "=r"(bf[ng][3])
                    : "r"(addr));
            }

            unsigned af[2][4];
#pragma unroll
            for (int mt = 0; mt < 2; mt++) {
                int r1 = wm * 32 + mt * 16 + g;
                __nv_bfloat162 x0 = __bfloat162bfloat162(c_s[r1 * CS_STRIDE + ii]);
                __nv_bfloat162 x1 = __bfloat162bfloat162(c_s[(r1 + 8) * CS_STRIDE + ii]);
                const __nv_bfloat162* p1 =
                    reinterpret_cast<const __nv_bfloat162*>(c_s + r1 * CS_STRIDE + jb + 2 * tg);
                const __nv_bfloat162* p2 =
                    reinterpret_cast<const __nv_bfloat162*>(c_s + (r1 + 8) * CS_STRIDE + jb + 2 * tg);
                __nv_bfloat162 a0 = __hmul2(x0, p1[0]);
                __nv_bfloat162 a1 = __hmul2(x1, p2[0]);
                __nv_bfloat162 a2 = __hmul2(x0, p1[4]);
                __nv_bfloat162 a3 = __hmul2(x1, p2[4]);
                af[mt][0] = *reinterpret_cast<unsigned*>(&a0);
                af[mt][1] = *reinterpret_cast<unsigned*>(&a1);
                af[mt][2] = *reinterpret_cast<unsigned*>(&a2);
                af[mt][3] = *reinterpret_cast<unsigned*>(&a3);
            }

#pragma unroll
            for (int mt = 0; mt < 2; mt++)
#pragma unroll
                for (int ng = 0; ng < 4; ng++) {
                    mma16816(acc[mt][2 * ng],     af[mt], bf[ng][0], bf[ng][1]);
                    mma16816(acc[mt][2 * ng + 1], af[mt], bf[ng][2], bf[ng][3]);
                }
        }
    }

#pragma unroll
    for (int mt = 0; mt < 2; mt++) {
        int r1 = mbase + wm * 32 + mt * 16 + g;
#pragma unroll
        for (int nn = 0; nn < 8; nn++) {
            int col = nbase + wn * 64 + nn * 8 + 2 * tg;
            float* dst = g_P + ((size_t)ks * B_ + r1) * NH_ + col;
            *reinterpret_cast<float2*>(dst) = make_float2(acc[mt][nn][0], acc[mt][nn][1]);
            *reinterpret_cast<float2*>(dst + (size_t)8 * NH_) =
                make_float2(acc[mt][nn][2], acc[mt][nn][3]);
        }
    }
}

// ---------------- kernel: reduce splits + bias + relu + pw2 + sigmoid ----------------
__global__ void k_finalize(const float* __restrict__ pb1, const float* __restrict__ pw2,
                           const float* __restrict__ pb2, float* __restrict__ out) {
    const int b = blockIdx.x;
    const int t = threadIdx.x;
    float local = 0.f;
    for (int n = t; n < NH_; n += 128) {
        size_t o = (size_t)b * NH_ + n;
        float v = 0.f;
#pragma unroll
        for (int s = 0; s < KSPLIT_; s++) v += g_P[(size_t)s * B_ * NH_ + o];
        v = fmaxf(v + pb1[n], 0.f);
        local += v * pw2[n];
    }
#pragma unroll
    for (int off = 16; off; off >>= 1) local += __shfl_down_sync(0xffffffffu, local, off);
    __shared__ float red[4];
    if ((t & 31) == 0) red[t >> 5] = local;
    __syncthreads();
    if (t == 0) {
        float s = red[0] + red[1] + red[2] + red[3] + pb2[0];
        out[b] = 1.f / (1.f + expf(-s));
    }
}

// ---------------- streams / events (created once at load, never freed) ----------------
static cudaStream_t g_sf, g_s1;
static cudaEvent_t  g_Eroot, g_Ef, g_E1;
static struct PipeInit {
    PipeInit() {
        cudaStreamCreateWithFlags(&g_sf, cudaStreamNonBlocking);
        cudaStreamCreateWithFlags(&g_s1, cudaStreamNonBlocking);
        cudaEventCreateWithFlags(&g_Eroot, cudaEventDisableTiming);
        cudaEventCreateWithFlags(&g_Ef, cudaEventDisableTiming);
        cudaEventCreateWithFlags(&g_E1, cudaEventDisableTiming);
    }
} g_pipe_init;

// ---------------- launch ----------------
extern "C" void kernel_launch(void* const* d_in, const int* in_sizes, int n_in,
                              void* d_out, int out_size) {
    const float* dense  = (const float*)d_in[0];
    const int*   sparse = (const int*)d_in[1];   // int32 on device
    const float* emb = (const float*)d_in[3];
    const float* dw1 = (const float*)d_in[4];
    const float* db1 = (const float*)d_in[5];
    const float* dw2 = (const float*)d_in[6];
    const float* db2 = (const float*)d_in[7];
    const float* sw1 = (const float*)d_in[8];
    const float* sb1 = (const float*)d_in[9];
    const float* sw2 = (const float*)d_in[10];
    const float* sb2 = (const float*)d_in[11];
    const float* pw1 = (const float*)d_in[12];
    const float* pb1 = (const float*)d_in[13];
    const float* pw2 = (const float*)d_in[14];
    const float* pb2 = (const float*)d_in[15];
    float* out = (float*)d_out;

    cudaFuncSetAttribute(k_gemm, cudaFuncAttributeMaxDynamicSharedMemorySize, SMEM_BYTES);

    // fork: features overlap the folds (small L2 footprint; no gemm running yet)
    cudaEventRecord(g_Eroot, 0);
    cudaStreamWaitEvent(g_sf, g_Eroot, 0);
    cudaStreamWaitEvent(g_s1, g_Eroot, 0);
    k_feat<<<FBLK_, 256, 0, g_sf>>>(dense, sparse, emb,
                                    dw1, db1, dw2, db2, sw1, sb1, sw2, sb2);
    cudaEventRecord(g_Ef, g_sf);

    // folds: two concurrent streams, 4 slices each -> double blocks in flight
    for (int z = 0; z < NFOLD_; z += 2) {
        k_fold<<<BLOCKS_PER_FOLD_, 256, 0, 0>>>(pw1, z);
        k_fold<<<BLOCKS_PER_FOLD_, 256, 0, g_s1>>>(pw1, z + 1);
    }
    cudaEventRecord(g_E1, g_s1);

    // join all producers, then ONE gemm launch (full L2 locality), then finalize
    cudaStreamWaitEvent(0, g_Ef, 0);
    cudaStreamWaitEvent(0, g_E1, 0);
    k_gemm<<<dim3(B_ / MT_, NH_ / NT_, KSPLIT_), 256, SMEM_BYTES>>>();
    k_finalize<<<B_, 128>>>(pb1, pw2, pb2, out);
}